// round 14
// baseline (speedup 1.0000x reference)
#include <cuda_runtime.h>
#include <cuda_fp16.h>
#include <cstdint>

#define B_ 4
#define N_ 4096
#define F_ 128
#define U_ 64
#define WHX_LD 64
#define TI 128
#define TJ 128
#define NT 32          // j-tiles
#define NBUF 6

// ---------------- scratch (device globals; no allocs allowed) ----------------
__device__ float  g_src[B_*N_];
__device__ float  g_dst[B_*N_];
__device__ float  g_maxd[B_];
__device__ float  g_colmean[B_*U_];
__device__ float  g_cpart[B_*16*U_];
__device__ float  g_mpart[B_*16];
__device__ __half g_Whx[(size_t)B_*N_*WHX_LD];

// ---------------- PTX helpers ----------------
__device__ __forceinline__ uint32_t smem_u32(const void* p) {
    return (uint32_t)__cvta_generic_to_shared(p);
}
__device__ __forceinline__ uint32_t h2u(__half2 v){
    return reinterpret_cast<uint32_t&>(v);
}
__device__ __forceinline__ __half2 u2h2(uint32_t v){
    return reinterpret_cast<__half2&>(v);
}
__device__ __forceinline__ uint32_t hex2(uint32_t x){
    uint32_t r;
    asm("ex2.approx.f16x2 %0, %1;" : "=r"(r) : "r"(x));
    return r;
}
__device__ __forceinline__ void ldsm_x4t(uint32_t a, uint32_t &r0, uint32_t &r1, uint32_t &r2, uint32_t &r3){
    asm volatile("ldmatrix.sync.aligned.m8n8.x4.trans.shared.b16 {%0,%1,%2,%3}, [%4];"
        : "=r"(r0),"=r"(r1),"=r"(r2),"=r"(r3) : "r"(a));
}
__device__ __forceinline__ void ldsm_x2t(uint32_t a, uint32_t &r0, uint32_t &r1){
    asm volatile("ldmatrix.sync.aligned.m8n8.x2.trans.shared.b16 {%0,%1}, [%2];"
        : "=r"(r0),"=r"(r1) : "r"(a));
}
__device__ __forceinline__ void mma16816(float* c, uint32_t a0,uint32_t a1,uint32_t a2,uint32_t a3,
                                         uint32_t b0,uint32_t b1){
    asm volatile("mma.sync.aligned.m16n8k16.row.col.f32.f16.f16.f32 "
      "{%0,%1,%2,%3}, {%4,%5,%6,%7}, {%8,%9}, {%0,%1,%2,%3};"
      : "+f"(c[0]),"+f"(c[1]),"+f"(c[2]),"+f"(c[3])
      : "r"(a0),"r"(a1),"r"(a2),"r"(a3),"r"(b0),"r"(b1));
}
__device__ __forceinline__ void cp_async16(uint32_t smem_addr, const void* gptr){
    asm volatile("cp.async.cg.shared.global [%0], [%1], 16;\n" :: "r"(smem_addr), "l"(gptr));
}
__device__ __forceinline__ void cp_commit(){ asm volatile("cp.async.commit_group;\n"); }
template<int Ng> __device__ __forceinline__ void cp_wait(){ asm volatile("cp.async.wait_group %0;\n"::"n"(Ng)); }

// logical row l (0..15) -> physical sB row, inverse of the A-fragment column perm
__device__ __forceinline__ int rowmap16(int l){
    return ((l >> 2) << 1) | (l & 1) | ((l & 2) << 2);
}

// ---------------- k1: Wh = h@W (4x4 register blocking), src/dst, Whx fp16 ----------------
#define K1_SMEM ((8192 + 128*68) * 4)
__global__ __launch_bounds__(256) void k1_proj(const float* __restrict__ h,
                                               const float* __restrict__ W,
                                               const float* __restrict__ a) {
    extern __shared__ float sm1[];
    float* sW32 = sm1;            // [128][64]
    float* sHT  = sm1 + 8192;     // [128][68]

    const int tid = threadIdx.x;
    const int r0  = blockIdx.x * 64;

    {
        const float4* Wv = (const float4*)W;
        float4* sWv = (float4*)sW32;
        #pragma unroll
        for (int i = tid; i < F_*U_/4; i += 256) sWv[i] = Wv[i];
    }
    {
        #pragma unroll
        for (int p = 0; p < 8; ++p) {
            const int idx = tid + p*256;
            const int r = idx & 63, c4 = idx >> 6;
            const float4 v = *(const float4*)(h + (size_t)(r0 + r)*F_ + c4*4);
            sHT[(c4*4+0)*68 + r] = v.x;
            sHT[(c4*4+1)*68 + r] = v.y;
            sHT[(c4*4+2)*68 + r] = v.z;
            sHT[(c4*4+3)*68 + r] = v.w;
        }
    }
    __syncthreads();

    const int tx = tid & 15;
    const int ty = tid >> 4;
    const int u0 = tx * 4;

    float acc[4][4];
    #pragma unroll
    for (int i = 0; i < 4; ++i)
        #pragma unroll
        for (int j = 0; j < 4; ++j) acc[i][j] = 0.f;

    #pragma unroll 4
    for (int f = 0; f < F_; ++f) {
        const float4 hv = *(const float4*)(sHT + f*68 + ty*4);
        const float4 wv = *(const float4*)(sW32 + f*64 + u0);
        acc[0][0]=fmaf(hv.x,wv.x,acc[0][0]); acc[0][1]=fmaf(hv.x,wv.y,acc[0][1]);
        acc[0][2]=fmaf(hv.x,wv.z,acc[0][2]); acc[0][3]=fmaf(hv.x,wv.w,acc[0][3]);
        acc[1][0]=fmaf(hv.y,wv.x,acc[1][0]); acc[1][1]=fmaf(hv.y,wv.y,acc[1][1]);
        acc[1][2]=fmaf(hv.y,wv.z,acc[1][2]); acc[1][3]=fmaf(hv.y,wv.w,acc[1][3]);
        acc[2][0]=fmaf(hv.z,wv.x,acc[2][0]); acc[2][1]=fmaf(hv.z,wv.y,acc[2][1]);
        acc[2][2]=fmaf(hv.z,wv.z,acc[2][2]); acc[2][3]=fmaf(hv.z,wv.w,acc[2][3]);
        acc[3][0]=fmaf(hv.w,wv.x,acc[3][0]); acc[3][1]=fmaf(hv.w,wv.y,acc[3][1]);
        acc[3][2]=fmaf(hv.w,wv.z,acc[3][2]); acc[3][3]=fmaf(hv.w,wv.w,acc[3][3]);
    }

    #pragma unroll
    for (int rr = 0; rr < 4; ++rr) {
        const int row = r0 + ty*4 + rr;
        __half2* wp = (__half2*)(g_Whx + (size_t)row*WHX_LD + u0);
        wp[0] = __floats2half2_rn(acc[rr][0], acc[rr][1]);
        wp[1] = __floats2half2_rn(acc[rr][2], acc[rr][3]);
    }

    float a1v[4], a2v[4];
    #pragma unroll
    for (int j = 0; j < 4; ++j) { a1v[j] = a[u0+j]; a2v[j] = a[U_ + u0 + j]; }
    #pragma unroll
    for (int rr = 0; rr < 4; ++rr) {
        float s = fmaf(acc[rr][0],a1v[0], fmaf(acc[rr][1],a1v[1], fmaf(acc[rr][2],a1v[2], acc[rr][3]*a1v[3])));
        float d = fmaf(acc[rr][0],a2v[0], fmaf(acc[rr][1],a2v[1], fmaf(acc[rr][2],a2v[2], acc[rr][3]*a2v[3])));
        #pragma unroll
        for (int off = 8; off > 0; off >>= 1) {
            s += __shfl_down_sync(0xffffffffu, s, off);
            d += __shfl_down_sync(0xffffffffu, d, off);
        }
        if (tx == 0) {
            g_src[r0 + ty*4 + rr] = s;
            g_dst[r0 + ty*4 + rr] = d;
        }
    }
}

// ---------------- k2a/k2b: max(dst), column means (fallback path) ----------------
__global__ __launch_bounds__(256) void k2a_partial() {
    const int b = blockIdx.x, part = blockIdx.y;
    const int tid = threadIdx.x;
    __shared__ float sred[256];

    float m = g_dst[b*N_ + part*256 + tid];
    sred[tid] = m; __syncthreads();
    #pragma unroll
    for (int s = 128; s > 0; s >>= 1) {
        if (tid < s) sred[tid] = fmaxf(sred[tid], sred[tid+s]);
        __syncthreads();
    }
    if (tid == 0) g_mpart[b*16 + part] = sred[0];
    __syncthreads();

    const int u = tid & 63, jg = tid >> 6;
    float sum = 0.f;
    #pragma unroll 8
    for (int j = jg; j < 256; j += 4)
        sum += __half2float(g_Whx[((size_t)b*N_ + part*256 + j)*WHX_LD + u]);
    sred[tid] = sum; __syncthreads();
    if (tid < 64)
        g_cpart[(b*16 + part)*64 + tid] = sred[tid] + sred[tid+64] + sred[tid+128] + sred[tid+192];
}

__global__ void k2b_combine() {
    const int b = blockIdx.x, u = threadIdx.x;
    float s = 0.f;
    #pragma unroll
    for (int p = 0; p < 16; ++p) s += g_cpart[(b*16 + p)*64 + u];
    g_colmean[b*U_ + u] = s * (1.0f / N_);
    if (u == 0) {
        float m = -1e30f;
        #pragma unroll
        for (int p = 0; p < 16; ++p) m = fmaxf(m, g_mpart[b*16 + p]);
        g_maxd[b] = m;
    }
}

// ---------------- k3: fused attention, k-split pairs, 6-buf Whx, 2-tile sync cadence ----------------
// smem: sdsth half[4096] @0 (8192B), sB[6] half[128][72] @8192 (+18432 each)
// combine phase reuses the sB area as float scratch.
#define SB_STRIDE 72
#define SB_BYTES  (128*SB_STRIDE*2)
#define SMEM_BYTES (8192 + NBUF*SB_BYTES)

__global__ __launch_bounds__(512, 1) void k3_attn(const int* __restrict__ adj,
        const float* __restrict__ gamma, const float* __restrict__ beta,
        const float* __restrict__ mmean, const float* __restrict__ mvar,
        float* __restrict__ out) {
    extern __shared__ char smem[];
    __half* sdsth = (__half*)smem;
    char*   sBb   = smem + 8192;

    const int tid    = threadIdx.x;
    const int b      = blockIdx.y;
    const int i0     = blockIdx.x * TI;
    const int lane   = tid & 31;
    const int wid    = tid >> 5;
    const int pairid = wid & 7;     // which 16-row slab
    const int khalf  = wid >> 3;    // which 64-col (k) half of the j-tile
    const int q      = lane & 3;
    const int q4     = q * 4;

    // rows owned by this warp's A fragments
    const int r1 = i0 + pairid*16 + (lane >> 2);
    const int r2 = r1 + 8;

    // ---- Whx tile cp.async (one commit per call; empty group when out of range) ----
    auto whx_commit = [&](int jt, int buf) {
        if (jt < NT) {
            char* sBx = sBb + buf*SB_BYTES;
            const char* gb = (const char*)(g_Whx + ((size_t)b*N_ + jt*TJ)*WHX_LD);
            #pragma unroll
            for (int p = 0; p < 2; ++p) {
                const int idx = tid + p*512;            // 1024 chunks of 16B
                const int row = idx >> 3, qc = idx & 7; // logical row, 16B chunk
                const int prow = (row & 0x70) | rowmap16(row & 15);
                cp_async16(smem_u32(sBx + prow*(SB_STRIDE*2) + qc*16),
                           gb + (size_t)row*128 + qc*16);
            }
        }
        cp_commit();
    };

    // ---- prologue: 4 tiles in flight ----
    whx_commit(0, 0); whx_commit(1, 1); whx_commit(2, 2); whx_commit(3, 3);

    // ones column at pad col 64 of every buffer (cp.async never touches cols 64..71)
    for (int i = tid; i < NBUF*128; i += 512) {
        const int buf = i >> 7, row = i & 127;
        *(uint4*)(sBb + buf*SB_BYTES + (row*SB_STRIDE + 64)*2) = make_uint4(0x3C00u, 0u, 0u, 0u);
    }

    const int4* ap1 = (const int4*)(adj + ((size_t)b*N_ + r1)*N_);
    const int4* ap2 = (const int4*)(adj + ((size_t)b*N_ + r2)*N_);
    // 4-slot ring = this warp's 4 slabs of one tile; refill slot for t+1 right after use
    int4 abuf[4][2];
    #pragma unroll
    for (int s = 0; s < 4; ++s) {
        abuf[s][0] = ap1[khalf*16 + s*4 + q];
        abuf[s][1] = ap2[khalf*16 + s*4 + q];
    }

    {   // stage dst row for this batch, converted to half (visible after first pair barrier)
        const float4* dp = (const float4*)(g_dst + b*N_);
        const int i = tid;           // 512 threads x 8 elems = 4096
        const float4 v0 = dp[2*i], v1 = dp[2*i+1];
        uint4 pk;
        pk.x = h2u(__floats2half2_rn(v0.x, v0.y));
        pk.y = h2u(__floats2half2_rn(v0.z, v0.w));
        pk.z = h2u(__floats2half2_rn(v1.x, v1.y));
        pk.w = h2u(__floats2half2_rn(v1.z, v1.w));
        *(uint4*)(sdsth + 8*i) = pk;
    }

    const float maxd = g_maxd[b];
    const float s1 = g_src[b*N_ + r1];
    const float s2 = g_src[b*N_ + r2];
    const float x1 = s1 + maxd, x2 = s2 + maxd;
    const float M1 = fmaxf(x1, 0.2f*x1);
    const float M2 = fmaxf(x2, 0.2f*x2);
    const float LOG2E = 1.44269504f;

    // half2 constants for the fused w pipeline
    const __half2 s1h  = __float2half2_rn(s1);
    const __half2 s2h  = __float2half2_rn(s2);
    const __half2 cm1  = __float2half2_rn(-M1 * LOG2E);
    const __half2 cm2  = __float2half2_rn(-M2 * LOG2E);
    const __half2 clg  = __float2half2_rn(LOG2E);
    const __half2 cpt  = __float2half2_rn(0.2f);

    float acc[8][4];
    #pragma unroll
    for (int t = 0; t < 8; ++t)
        #pragma unroll
        for (int k = 0; k < 4; ++k) acc[t][k] = 0.f;
    float accd[4] = {0.f, 0.f, 0.f, 0.f};   // denominator via ones-column MMA

    const uint32_t sb0 = smem_u32(sBb);
    const uint32_t off_b = (uint32_t)(((lane & 15)*SB_STRIDE + (lane >> 4)*8) * 2);
    const uint32_t off_e = (uint32_t)(((lane & 15)*SB_STRIDE + 64) * 2);

    int rbuf = 0;   // buffer of tile being processed
    int wbuf = 4;   // next prefetch buffer

    for (int p = 0; p < NT/2; ++p) {
        cp_wait<2>();
        __syncthreads();
        // refill: targets bufs read during pair p-1, confirmed free by the barrier above
        whx_commit(2*p+4, wbuf); wbuf = (wbuf+1 == NBUF) ? 0 : wbuf+1;
        whx_commit(2*p+5, wbuf); wbuf = (wbuf+1 == NBUF) ? 0 : wbuf+1;

        #pragma unroll
        for (int half = 0; half < 2; ++half) {
            const int t = 2*p + half;
            const uint32_t bbase = sb0 + (uint32_t)rbuf*SB_BYTES + off_b;
            const uint32_t ebase = sb0 + (uint32_t)rbuf*SB_BYTES + off_e;
            const __half* dbase = sdsth + t*TJ + khalf*64 + q4;

            #pragma unroll
            for (int kk = 0; kk < 4; ++kk) {
                const int kabs = khalf*4 + kk;      // absolute k-slab in the 128-wide tile
                const uint2 dp = *(const uint2*)(dbase + kk*16);
                const __half2 dlo = u2h2(dp.x), dhi = u2h2(dp.y);
                const int4 A1 = abuf[kk][0];
                const int4 A2 = abuf[kk][1];

                // refill this slot for tile t+1 (phase-consistent: 4 slots, 4 slabs/tile)
                if (t < NT-1) {
                    abuf[kk][0] = ap1[(t+1)*32 + khalf*16 + kk*4 + q];
                    abuf[kk][1] = ap2[(t+1)*32 + khalf*16 + kk*4 + q];
                }

                // row r1: w = mask * 2^((leaky(s+d) - M) * log2e), all fp16x2
                __half2 t0 = __hadd2(s1h, dlo), t1 = __hadd2(s1h, dhi);
                t0 = __hmax2(t0, __hmul2(cpt, t0));
                t1 = __hmax2(t1, __hmul2(cpt, t1));
                const uint32_t e0 = hex2(h2u(__hfma2(t0, clg, cm1)));
                const uint32_t e1 = hex2(h2u(__hfma2(t1, clg, cm1)));
                // adj values are 0/1 -> build half2 {1.0,1.0} masks with 2 IMADs
                const uint32_t m00 = (uint32_t)A1.x*0x3C00u + (uint32_t)A1.y*0x3C000000u;
                const uint32_t m01 = (uint32_t)A1.z*0x3C00u + (uint32_t)A1.w*0x3C000000u;
                const uint32_t a0  = h2u(__hmul2(u2h2(e0), u2h2(m00)));
                const uint32_t a2r = h2u(__hmul2(u2h2(e1), u2h2(m01)));

                // row r2
                __half2 z0 = __hadd2(s2h, dlo), z1 = __hadd2(s2h, dhi);
                z0 = __hmax2(z0, __hmul2(cpt, z0));
                z1 = __hmax2(z1, __hmul2(cpt, z1));
                const uint32_t f0 = hex2(h2u(__hfma2(z0, clg, cm2)));
                const uint32_t f1 = hex2(h2u(__hfma2(z1, clg, cm2)));
                const uint32_t m10 = (uint32_t)A2.x*0x3C00u + (uint32_t)A2.y*0x3C000000u;
                const uint32_t m11 = (uint32_t)A2.z*0x3C00u + (uint32_t)A2.w*0x3C000000u;
                const uint32_t a1  = h2u(__hmul2(u2h2(f0), u2h2(m10)));
                const uint32_t a3  = h2u(__hmul2(u2h2(f1), u2h2(m11)));

                #pragma unroll
                for (int nt2 = 0; nt2 < 4; ++nt2) {
                    uint32_t b0,b1,b2,b3;
                    ldsm_x4t(bbase + (uint32_t)(kabs*16*SB_STRIDE*2 + nt2*32), b0,b1,b2,b3);
                    mma16816(acc[2*nt2],   a0,a1,a2r,a3, b0,b1);
                    mma16816(acc[2*nt2+1], a0,a1,a2r,a3, b2,b3);
                }
                {   // denominator: ones column (col 64)
                    uint32_t d0,d1r;
                    ldsm_x2t(ebase + (uint32_t)(kabs*16*SB_STRIDE*2), d0,d1r);
                    mma16816(accd, a0,a1,a2r,a3, d0,d1r);
                }
            }
            rbuf = (rbuf+1 == NBUF) ? 0 : rbuf+1;
        }
    }

    // ---- combine k-halves through smem (sB area is dead now) ----
    __syncthreads();
    float* scomb = (float*)sBb;
    const int cidx = (pairid*32 + lane)*40;
    if (khalf == 1) {
        #pragma unroll
        for (int nt = 0; nt < 8; ++nt)
            *(float4*)(scomb + cidx + nt*4) = make_float4(acc[nt][0],acc[nt][1],acc[nt][2],acc[nt][3]);
        *(float4*)(scomb + cidx + 32) = make_float4(accd[0],accd[1],accd[2],accd[3]);
    }
    __syncthreads();
    if (khalf == 0) {
        #pragma unroll
        for (int nt = 0; nt < 8; ++nt) {
            const float4 v = *(const float4*)(scomb + cidx + nt*4);
            acc[nt][0]+=v.x; acc[nt][1]+=v.y; acc[nt][2]+=v.z; acc[nt][3]+=v.w;
        }
        const float4 vd = *(const float4*)(scomb + cidx + 32);
        accd[0]+=vd.x; accd[2]+=vd.z;

        // ---- epilogue: normalize, BN, ReLU, store (full 64 cols, rows r1/r2) ----
        const float dl = __shfl_sync(0xffffffffu, accd[0], lane & ~3);
        const float dh = __shfl_sync(0xffffffffu, accd[2], lane & ~3);
        const float invl = (dl > 0.f) ? 1.0f/dl : 0.f;
        const float invh = (dh > 0.f) ? 1.0f/dh : 0.f;

        const int rloc = pairid*16 + (lane >> 2);
        #pragma unroll
        for (int nt = 0; nt < 8; ++nt) {
            const int u0 = nt*8 + 2*q, u1 = u0 + 1;
            const float sc0 = gamma[u0] * rsqrtf(mvar[u0] + 1e-3f);
            const float sc1 = gamma[u1] * rsqrtf(mvar[u1] + 1e-3f);
            const float bi0 = beta[u0] - mmean[u0]*sc0;
            const float bi1 = beta[u1] - mmean[u1]*sc1;

            float v00 = (dl > 0.f) ? acc[nt][0]*invl : g_colmean[b*U_ + u0];
            float v01 = (dl > 0.f) ? acc[nt][1]*invl : g_colmean[b*U_ + u1];
            float v10 = (dh > 0.f) ? acc[nt][2]*invh : g_colmean[b*U_ + u0];
            float v11 = (dh > 0.f) ? acc[nt][3]*invh : g_colmean[b*U_ + u1];

            float2 lo = make_float2(fmaxf(fmaf(v00, sc0, bi0), 0.f), fmaxf(fmaf(v01, sc1, bi1), 0.f));
            float2 hi = make_float2(fmaxf(fmaf(v10, sc0, bi0), 0.f), fmaxf(fmaf(v11, sc1, bi1), 0.f));
            *(float2*)(out + ((size_t)(b*N_ + i0 + rloc    ))*U_ + u0) = lo;
            *(float2*)(out + ((size_t)(b*N_ + i0 + rloc + 8))*U_ + u0) = hi;
        }
    }
}

// ---------------- launch ----------------
extern "C" void kernel_launch(void* const* d_in, const int* in_sizes, int n_in,
                              void* d_out, int out_size) {
    (void)in_sizes; (void)n_in; (void)out_size;
    const float* h     = (const float*)d_in[0];
    const int*   adj   = (const int*)  d_in[1];
    const float* W     = (const float*)d_in[2];
    const float* a     = (const float*)d_in[3];
    const float* gamma = (const float*)d_in[4];
    const float* beta  = (const float*)d_in[5];
    const float* mmean = (const float*)d_in[6];
    const float* mvar  = (const float*)d_in[7];
    float* out = (float*)d_out;

    cudaFuncSetAttribute(k1_proj, cudaFuncAttributeMaxDynamicSharedMemorySize, K1_SMEM);
    cudaFuncSetAttribute(k3_attn, cudaFuncAttributeMaxDynamicSharedMemorySize, SMEM_BYTES);

    k1_proj<<<B_*N_/64, 256, K1_SMEM>>>(h, W, a);
    dim3 g2(B_, 16);
    k2a_partial<<<g2, 256>>>();
    k2b_combine<<<B_, 64>>>();
    dim3 g3(N_/TI, B_);
    k3_attn<<<g3, 512, SMEM_BYTES>>>(adj, gamma, beta, mmean, mvar, out);
}

// round 17
// speedup vs baseline: 1.1304x; 1.1304x over previous
#include <cuda_runtime.h>
#include <cuda_fp16.h>
#include <cstdint>

#define B_ 4
#define N_ 4096
#define F_ 128
#define U_ 64
#define WHX_LD 64
#define TI 128
#define TJ 128
#define NT 32          // j-tiles
#define NBUF 6

// ---------------- scratch (device globals; no allocs allowed) ----------------
__device__ float  g_src[B_*N_];
__device__ float  g_dst[B_*N_];
__device__ float  g_maxd[B_];
__device__ float  g_colmean[B_*U_];
__device__ float  g_cpart[128*U_];
__device__ float  g_mpart[128];
__device__ __half g_Whx[(size_t)B_*N_*WHX_LD];

// ---------------- PTX helpers ----------------
__device__ __forceinline__ uint32_t smem_u32(const void* p) {
    return (uint32_t)__cvta_generic_to_shared(p);
}
__device__ __forceinline__ uint32_t h2u(__half2 v){
    return reinterpret_cast<uint32_t&>(v);
}
__device__ __forceinline__ __half2 u2h2(uint32_t v){
    return reinterpret_cast<__half2&>(v);
}
__device__ __forceinline__ uint32_t hex2(uint32_t x){
    uint32_t r;
    asm("ex2.approx.f16x2 %0, %1;" : "=r"(r) : "r"(x));
    return r;
}
__device__ __forceinline__ void ldsm_x4(uint32_t a, uint32_t &r0, uint32_t &r1, uint32_t &r2, uint32_t &r3){
    asm volatile("ldmatrix.sync.aligned.m8n8.x4.shared.b16 {%0,%1,%2,%3}, [%4];"
        : "=r"(r0),"=r"(r1),"=r"(r2),"=r"(r3) : "r"(a));
}
__device__ __forceinline__ void ldsm_x4t(uint32_t a, uint32_t &r0, uint32_t &r1, uint32_t &r2, uint32_t &r3){
    asm volatile("ldmatrix.sync.aligned.m8n8.x4.trans.shared.b16 {%0,%1,%2,%3}, [%4];"
        : "=r"(r0),"=r"(r1),"=r"(r2),"=r"(r3) : "r"(a));
}
__device__ __forceinline__ void ldsm_x2t(uint32_t a, uint32_t &r0, uint32_t &r1){
    asm volatile("ldmatrix.sync.aligned.m8n8.x2.trans.shared.b16 {%0,%1}, [%2];"
        : "=r"(r0),"=r"(r1) : "r"(a));
}
__device__ __forceinline__ void mma16816(float* c, uint32_t a0,uint32_t a1,uint32_t a2,uint32_t a3,
                                         uint32_t b0,uint32_t b1){
    asm volatile("mma.sync.aligned.m16n8k16.row.col.f32.f16.f16.f32 "
      "{%0,%1,%2,%3}, {%4,%5,%6,%7}, {%8,%9}, {%0,%1,%2,%3};"
      : "+f"(c[0]),"+f"(c[1]),"+f"(c[2]),"+f"(c[3])
      : "r"(a0),"r"(a1),"r"(a2),"r"(a3),"r"(b0),"r"(b1));
}
__device__ __forceinline__ void cp_async16(uint32_t smem_addr, const void* gptr){
    asm volatile("cp.async.cg.shared.global [%0], [%1], 16;\n" :: "r"(smem_addr), "l"(gptr));
}
__device__ __forceinline__ void cp_commit(){ asm volatile("cp.async.commit_group;\n"); }
template<int Ng> __device__ __forceinline__ void cp_wait(){ asm volatile("cp.async.wait_group %0;\n"::"n"(Ng)); }

// logical row l (0..15) -> physical sB row, inverse of the A-fragment column perm
__device__ __forceinline__ int rowmap16(int l){
    return ((l >> 2) << 1) | (l & 1) | ((l & 2) << 2);
}

// ---------------- k1: Wh = h@W via fp16 mma.sync; src/dst; fused colmean/max partials ----------------
// smem: sH half[128][136] (34816B) + sW half[128][72] (18432B) + scomb f32[8*64] (2048B) + smax[8]
#define K1_SH_H   0
#define K1_SH_W   (128*136)
#define K1_SH_CMB (K1_SH_W + 128*72)          // in halves; float area starts here (aligned 4B)
#define K1_SMEM   ((K1_SH_CMB)*2 + 8*64*4 + 32)
__global__ __launch_bounds__(256) void k1_proj(const float* __restrict__ h,
                                               const float* __restrict__ W,
                                               const float* __restrict__ a) {
    extern __shared__ __half sm1h[];
    __half* sH = sm1h;                  // [128][136]
    __half* sW = sm1h + K1_SH_W;        // [128][72]
    float*  scomb = (float*)(sm1h + K1_SH_CMB);  // [8][64]
    float*  smax  = scomb + 8*64;                // [8]

    const int tid  = threadIdx.x;
    const int lane = tid & 31;
    const int wid  = tid >> 5;
    const int q    = lane & 3;
    const int r0   = blockIdx.x * 128;

    // stage h tile (fp32 -> fp16), rows r0..r0+127
    #pragma unroll
    for (int p = 0; p < 16; ++p) {
        const int idx = tid + p*256;            // 4096 float4
        const int r = idx >> 5, c4 = idx & 31;
        const float4 v = *(const float4*)(h + (size_t)(r0 + r)*F_ + c4*4);
        uint2 pk;
        pk.x = h2u(__floats2half2_rn(v.x, v.y));
        pk.y = h2u(__floats2half2_rn(v.z, v.w));
        *(uint2*)(sH + r*136 + c4*4) = pk;
    }
    // stage W (fp32 -> fp16), [128 f][64 u] at stride 72
    #pragma unroll
    for (int p = 0; p < 8; ++p) {
        const int idx = tid + p*256;            // 2048 float4
        const int r = idx >> 4, c4 = idx & 15;
        const float4 v = *(const float4*)(W + (size_t)r*U_ + c4*4);
        uint2 pk;
        pk.x = h2u(__floats2half2_rn(v.x, v.y));
        pk.y = h2u(__floats2half2_rn(v.z, v.w));
        *(uint2*)(sW + r*72 + c4*4) = pk;
    }
    __syncthreads();

    const uint32_t a_base = smem_u32(sH) + (uint32_t)(((16*wid + (lane & 15))*136 + (lane >> 4)*8) * 2);
    const uint32_t b_base = smem_u32(sW) + (uint32_t)(((lane & 15)*72 + (lane >> 4)*8) * 2);

    float acc[8][4];
    #pragma unroll
    for (int t = 0; t < 8; ++t)
        #pragma unroll
        for (int k = 0; k < 4; ++k) acc[t][k] = 0.f;

    #pragma unroll
    for (int kk = 0; kk < 8; ++kk) {
        uint32_t a0,a1r,a2,a3;
        ldsm_x4(a_base + kk*32, a0,a1r,a2,a3);
        #pragma unroll
        for (int nt2 = 0; nt2 < 4; ++nt2) {
            uint32_t b0,b1,b2,b3;
            ldsm_x4t(b_base + (uint32_t)(kk*16*72*2 + nt2*32), b0,b1,b2,b3);
            mma16816(acc[2*nt2],   a0,a1r,a2,a3, b0,b1);
            mma16816(acc[2*nt2+1], a0,a1r,a2,a3, b2,b3);
        }
    }

    // rows owned by this thread
    const int rloc1 = wid*16 + (lane >> 2);
    const int rloc2 = rloc1 + 8;

    // ---- write Whx fp16 [row][64] ----
    #pragma unroll
    for (int nt = 0; nt < 8; ++nt) {
        const int u0 = nt*8 + 2*q;
        *(__half2*)(g_Whx + (size_t)(r0 + rloc1)*WHX_LD + u0) = __floats2half2_rn(acc[nt][0], acc[nt][1]);
        *(__half2*)(g_Whx + (size_t)(r0 + rloc2)*WHX_LD + u0) = __floats2half2_rn(acc[nt][2], acc[nt][3]);
    }

    // ---- src/dst per row (deterministic shfl over q) ----
    float s1 = 0.f, d1 = 0.f, s2 = 0.f, d2 = 0.f;
    #pragma unroll
    for (int nt = 0; nt < 8; ++nt) {
        const int u0 = nt*8 + 2*q;
        const float A0 = a[u0], A1 = a[u0+1];
        const float B0 = a[U_ + u0], B1 = a[U_ + u0 + 1];
        s1 += acc[nt][0]*A0 + acc[nt][1]*A1;
        d1 += acc[nt][0]*B0 + acc[nt][1]*B1;
        s2 += acc[nt][2]*A0 + acc[nt][3]*A1;
        d2 += acc[nt][2]*B0 + acc[nt][3]*B1;
    }
    #pragma unroll
    for (int off = 1; off <= 2; off <<= 1) {
        s1 += __shfl_xor_sync(0xffffffffu, s1, off);
        d1 += __shfl_xor_sync(0xffffffffu, d1, off);
        s2 += __shfl_xor_sync(0xffffffffu, s2, off);
        d2 += __shfl_xor_sync(0xffffffffu, d2, off);
    }
    if (q == 0) {
        g_src[r0 + rloc1] = s1; g_dst[r0 + rloc1] = d1;
        g_src[r0 + rloc2] = s2; g_dst[r0 + rloc2] = d2;
    }

    // ---- fused partials: column sums over this block's 128 rows + max(dst) ----
    float cs0[8], cs1[8];
    #pragma unroll
    for (int nt = 0; nt < 8; ++nt) {
        cs0[nt] = acc[nt][0] + acc[nt][2];
        cs1[nt] = acc[nt][1] + acc[nt][3];
    }
    #pragma unroll
    for (int off = 4; off <= 16; off <<= 1) {
        #pragma unroll
        for (int nt = 0; nt < 8; ++nt) {
            cs0[nt] += __shfl_xor_sync(0xffffffffu, cs0[nt], off);
            cs1[nt] += __shfl_xor_sync(0xffffffffu, cs1[nt], off);
        }
    }
    if (lane < 4) {
        #pragma unroll
        for (int nt = 0; nt < 8; ++nt) {
            scomb[wid*64 + nt*8 + 2*q]     = cs0[nt];
            scomb[wid*64 + nt*8 + 2*q + 1] = cs1[nt];
        }
    }
    float dm = fmaxf(d1, d2);
    #pragma unroll
    for (int off = 1; off <= 16; off <<= 1)
        dm = fmaxf(dm, __shfl_xor_sync(0xffffffffu, dm, off));
    if (lane == 0) smax[wid] = dm;
    __syncthreads();

    if (tid < 64) {
        float s = 0.f;
        #pragma unroll
        for (int w = 0; w < 8; ++w) s += scomb[w*64 + tid];
        g_cpart[blockIdx.x*64 + tid] = s;
    }
    if (tid == 0) {
        float m = smax[0];
        #pragma unroll
        for (int w = 1; w < 8; ++w) m = fmaxf(m, smax[w]);
        g_mpart[blockIdx.x] = m;
    }
}

// ---------------- k2b: combine 32 block-partials per batch ----------------
__global__ void k2b_combine() {
    const int b = blockIdx.x, u = threadIdx.x;   // 64 threads
    float s = 0.f;
    #pragma unroll
    for (int p = 0; p < 32; ++p) s += g_cpart[(b*32 + p)*64 + u];
    g_colmean[b*U_ + u] = s * (1.0f / N_);
    if (u == 0) {
        float m = -1e30f;
        #pragma unroll
        for (int p = 0; p < 32; ++p) m = fmaxf(m, g_mpart[b*32 + p]);
        g_maxd[b] = m;
    }
}

// ---------------- k3: fused attention, k-split pairs, 6-buf Whx, 2-tile sync cadence ----------------
#define SB_STRIDE 72
#define SB_BYTES  (128*SB_STRIDE*2)
#define SMEM_BYTES (8192 + NBUF*SB_BYTES)

__global__ __launch_bounds__(512, 1) void k3_attn(const int* __restrict__ adj,
        const float* __restrict__ gamma, const float* __restrict__ beta,
        const float* __restrict__ mmean, const float* __restrict__ mvar,
        float* __restrict__ out) {
    extern __shared__ char smem[];
    __half* sdsth = (__half*)smem;
    char*   sBb   = smem + 8192;

    const int tid    = threadIdx.x;
    const int b      = blockIdx.y;
    const int i0     = blockIdx.x * TI;
    const int lane   = tid & 31;
    const int wid    = tid >> 5;
    const int pairid = wid & 7;     // which 16-row slab
    const int khalf  = wid >> 3;    // which 64-col (k) half of the j-tile
    const int q      = lane & 3;

    // rows owned by this warp's A fragments
    const int r1 = i0 + pairid*16 + (lane >> 2);
    const int r2 = r1 + 8;

    // ---- Whx tile cp.async (one commit per call; empty group when out of range) ----
    auto whx_commit = [&](int jt, int buf) {
        if (jt < NT) {
            char* sBx = sBb + buf*SB_BYTES;
            const char* gb = (const char*)(g_Whx + ((size_t)b*N_ + jt*TJ)*WHX_LD);
            #pragma unroll
            for (int p = 0; p < 2; ++p) {
                const int idx = tid + p*512;            // 1024 chunks of 16B
                const int row = idx >> 3, qc = idx & 7; // logical row, 16B chunk
                const int prow = (row & 0x70) | rowmap16(row & 15);
                cp_async16(smem_u32(sBx + prow*(SB_STRIDE*2) + qc*16),
                           gb + (size_t)row*128 + qc*16);
            }
        }
        cp_commit();
    };

    // ---- prologue: 4 tiles in flight ----
    whx_commit(0, 0); whx_commit(1, 1); whx_commit(2, 2); whx_commit(3, 3);

    // ones column at pad col 64 of every buffer (cp.async never touches cols 64..71)
    for (int i = tid; i < NBUF*128; i += 512) {
        const int buf = i >> 7, row = i & 127;
        *(uint4*)(sBb + buf*SB_BYTES + (row*SB_STRIDE + 64)*2) = make_uint4(0x3C00u, 0u, 0u, 0u);
    }

    const int4* ap1 = (const int4*)(adj + ((size_t)b*N_ + r1)*N_);
    const int4* ap2 = (const int4*)(adj + ((size_t)b*N_ + r2)*N_);
    int4 abuf[4][2];
    #pragma unroll
    for (int s = 0; s < 4; ++s) {
        abuf[s][0] = ap1[khalf*16 + s*4 + q];
        abuf[s][1] = ap2[khalf*16 + s*4 + q];
    }

    {   // stage dst row for this batch, converted to half
        const float4* dp = (const float4*)(g_dst + b*N_);
        const float4 v0 = dp[2*tid], v1 = dp[2*tid+1];
        uint4 pk;
        pk.x = h2u(__floats2half2_rn(v0.x, v0.y));
        pk.y = h2u(__floats2half2_rn(v0.z, v0.w));
        pk.z = h2u(__floats2half2_rn(v1.x, v1.y));
        pk.w = h2u(__floats2half2_rn(v1.z, v1.w));
        *(uint4*)(sdsth + 8*tid) = pk;
    }

    const float maxd = g_maxd[b];
    const float s1 = g_src[b*N_ + r1];
    const float s2 = g_src[b*N_ + r2];
    const float x1 = s1 + maxd, x2 = s2 + maxd;
    const float M1 = fmaxf(x1, 0.2f*x1);
    const float M2 = fmaxf(x2, 0.2f*x2);
    const float LOG2E = 1.44269504f;

    const __half2 s1h  = __float2half2_rn(s1);
    const __half2 s2h  = __float2half2_rn(s2);
    const __half2 cm1  = __float2half2_rn(-M1 * LOG2E);
    const __half2 cm2  = __float2half2_rn(-M2 * LOG2E);
    const __half2 clg  = __float2half2_rn(LOG2E);
    const __half2 cpt  = __float2half2_rn(0.2f);

    float acc[8][4];
    #pragma unroll
    for (int t = 0; t < 8; ++t)
        #pragma unroll
        for (int k = 0; k < 4; ++k) acc[t][k] = 0.f;
    float accd[4] = {0.f, 0.f, 0.f, 0.f};

    const uint32_t sb0 = smem_u32(sBb);
    const uint32_t off_b = (uint32_t)(((lane & 15)*SB_STRIDE + (lane >> 4)*8) * 2);
    const uint32_t off_e = (uint32_t)(((lane & 15)*SB_STRIDE + 64) * 2);

    int rbuf = 0;
    int wbuf = 4;

    for (int p = 0; p < NT/2; ++p) {
        cp_wait<2>();
        __syncthreads();
        whx_commit(2*p+4, wbuf); wbuf = (wbuf+1 == NBUF) ? 0 : wbuf+1;
        whx_commit(2*p+5, wbuf); wbuf = (wbuf+1 == NBUF) ? 0 : wbuf+1;

        #pragma unroll
        for (int half = 0; half < 2; ++half) {
            const int t = 2*p + half;
            const uint32_t bbase = sb0 + (uint32_t)rbuf*SB_BYTES + off_b;
            const uint32_t ebase = sb0 + (uint32_t)rbuf*SB_BYTES + off_e;
            const __half* dbase = sdsth + t*TJ + khalf*64 + q*4;

            #pragma unroll
            for (int kk = 0; kk < 4; ++kk) {
                const int kabs = khalf*4 + kk;
                const uint2 dp = *(const uint2*)(dbase + kk*16);
                const __half2 dlo = u2h2(dp.x), dhi = u2h2(dp.y);
                const int4 A1 = abuf[kk][0];
                const int4 A2 = abuf[kk][1];

                if (t < NT-1) {
                    abuf[kk][0] = ap1[(t+1)*32 + khalf*16 + kk*4 + q];
                    abuf[kk][1] = ap2[(t+1)*32 + khalf*16 + kk*4 + q];
                }

                __half2 t0 = __hadd2(s1h, dlo), t1 = __hadd2(s1h, dhi);
                t0 = __hmax2(t0, __hmul2(cpt, t0));
                t1 = __hmax2(t1, __hmul2(cpt, t1));
                const uint32_t e0 = hex2(h2u(__hfma2(t0, clg, cm1)));
                const uint32_t e1 = hex2(h2u(__hfma2(t1, clg, cm1)));
                const uint32_t m00 = (uint32_t)A1.x*0x3C00u + (uint32_t)A1.y*0x3C000000u;
                const uint32_t m01 = (uint32_t)A1.z*0x3C00u + (uint32_t)A1.w*0x3C000000u;
                const uint32_t a0  = h2u(__hmul2(u2h2(e0), u2h2(m00)));
                const uint32_t a2r = h2u(__hmul2(u2h2(e1), u2h2(m01)));

                __half2 z0 = __hadd2(s2h, dlo), z1 = __hadd2(s2h, dhi);
                z0 = __hmax2(z0, __hmul2(cpt, z0));
                z1 = __hmax2(z1, __hmul2(cpt, z1));
                const uint32_t f0 = hex2(h2u(__hfma2(z0, clg, cm2)));
                const uint32_t f1 = hex2(h2u(__hfma2(z1, clg, cm2)));
                const uint32_t m10 = (uint32_t)A2.x*0x3C00u + (uint32_t)A2.y*0x3C000000u;
                const uint32_t m11 = (uint32_t)A2.z*0x3C00u + (uint32_t)A2.w*0x3C000000u;
                const uint32_t a1  = h2u(__hmul2(u2h2(f0), u2h2(m10)));
                const uint32_t a3  = h2u(__hmul2(u2h2(f1), u2h2(m11)));

                #pragma unroll
                for (int nt2 = 0; nt2 < 4; ++nt2) {
                    uint32_t b0,b1,b2,b3;
                    ldsm_x4t(bbase + (uint32_t)(kabs*16*SB_STRIDE*2 + nt2*32), b0,b1,b2,b3);
                    mma16816(acc[2*nt2],   a0,a1,a2r,a3, b0,b1);
                    mma16816(acc[2*nt2+1], a0,a1,a2r,a3, b2,b3);
                }
                {
                    uint32_t d0,d1r;
                    ldsm_x2t(ebase + (uint32_t)(kabs*16*SB_STRIDE*2), d0,d1r);
                    mma16816(accd, a0,a1,a2r,a3, d0,d1r);
                }
            }
            rbuf = (rbuf+1 == NBUF) ? 0 : rbuf+1;
        }
    }

    // ---- combine k-halves through smem (sB area is dead now) ----
    __syncthreads();
    float* scomb = (float*)sBb;
    const int cidx = (pairid*32 + lane)*40;
    if (khalf == 1) {
        #pragma unroll
        for (int nt = 0; nt < 8; ++nt)
            *(float4*)(scomb + cidx + nt*4) = make_float4(acc[nt][0],acc[nt][1],acc[nt][2],acc[nt][3]);
        *(float4*)(scomb + cidx + 32) = make_float4(accd[0],accd[1],accd[2],accd[3]);
    }
    __syncthreads();
    if (khalf == 0) {
        #pragma unroll
        for (int nt = 0; nt < 8; ++nt) {
            const float4 v = *(const float4*)(scomb + cidx + nt*4);
            acc[nt][0]+=v.x; acc[nt][1]+=v.y; acc[nt][2]+=v.z; acc[nt][3]+=v.w;
        }
        const float4 vd = *(const float4*)(scomb + cidx + 32);
        accd[0]+=vd.x; accd[2]+=vd.z;

        const float dl = __shfl_sync(0xffffffffu, accd[0], lane & ~3);
        const float dh = __shfl_sync(0xffffffffu, accd[2], lane & ~3);
        const float invl = (dl > 0.f) ? 1.0f/dl : 0.f;
        const float invh = (dh > 0.f) ? 1.0f/dh : 0.f;

        const int rloc = pairid*16 + (lane >> 2);
        #pragma unroll
        for (int nt = 0; nt < 8; ++nt) {
            const int u0 = nt*8 + 2*q, u1 = u0 + 1;
            const float sc0 = gamma[u0] * rsqrtf(mvar[u0] + 1e-3f);
            const float sc1 = gamma[u1] * rsqrtf(mvar[u1] + 1e-3f);
            const float bi0 = beta[u0] - mmean[u0]*sc0;
            const float bi1 = beta[u1] - mmean[u1]*sc1;

            float v00 = (dl > 0.f) ? acc[nt][0]*invl : g_colmean[b*U_ + u0];
            float v01 = (dl > 0.f) ? acc[nt][1]*invl : g_colmean[b*U_ + u1];
            float v10 = (dh > 0.f) ? acc[nt][2]*invh : g_colmean[b*U_ + u0];
            float v11 = (dh > 0.f) ? acc[nt][3]*invh : g_colmean[b*U_ + u1];

            float2 lo = make_float2(fmaxf(fmaf(v00, sc0, bi0), 0.f), fmaxf(fmaf(v01, sc1, bi1), 0.f));
            float2 hi = make_float2(fmaxf(fmaf(v10, sc0, bi0), 0.f), fmaxf(fmaf(v11, sc1, bi1), 0.f));
            *(float2*)(out + ((size_t)(b*N_ + i0 + rloc    ))*U_ + u0) = lo;
            *(float2*)(out + ((size_t)(b*N_ + i0 + rloc + 8))*U_ + u0) = hi;
        }
    }
}

// ---------------- launch ----------------
extern "C" void kernel_launch(void* const* d_in, const int* in_sizes, int n_in,
                              void* d_out, int out_size) {
    (void)in_sizes; (void)n_in; (void)out_size;
    const float* h     = (const float*)d_in[0];
    const int*   adj   = (const int*)  d_in[1];
    const float* W     = (const float*)d_in[2];
    const float* a     = (const float*)d_in[3];
    const float* gamma = (const float*)d_in[4];
    const float* beta  = (const float*)d_in[5];
    const float* mmean = (const float*)d_in[6];
    const float* mvar  = (const float*)d_in[7];
    float* out = (float*)d_out;

    cudaFuncSetAttribute(k1_proj, cudaFuncAttributeMaxDynamicSharedMemorySize, K1_SMEM);
    cudaFuncSetAttribute(k3_attn, cudaFuncAttributeMaxDynamicSharedMemorySize, SMEM_BYTES);

    k1_proj<<<B_*N_/128, 256, K1_SMEM>>>(h, W, a);
    k2b_combine<<<B_, 64>>>();
    dim3 g3(N_/TI, B_);
    k3_attn<<<g3, 512, SMEM_BYTES>>>(adj, gamma, beta, mmean, mvar, out);
}